// round 2
// baseline (speedup 1.0000x reference)
#include <cuda_runtime.h>
#include <math.h>

#define N_RAYS_C 131072
#define N_HIT_C  65536

// ---------------- device state (zero at load; every replay restores zeros)
__device__ unsigned g_key[N_RAYS_C];       // err bits (valid) or 0xFFFFFFFF
__device__ unsigned g_histA[65536];        // top-16-bit histogram
__device__ unsigned g_histB[2][65536];     // low-16-bit histograms (per prefix)
__device__ unsigned g_nvalid;
__device__ unsigned g_cnt1, g_cnt2, g_cnt3;
__device__ unsigned g_prefTop[2];          // selected top-16 bins (or 0xFFFFFFFF sentinel)
__device__ unsigned g_rankLow[2];          // residual rank within top bin
__device__ unsigned g_empty;
__device__ float    g_thresh;
__device__ float    g_sums[4];             // sum_dm, sum_m, acc_neighbor, acc_empty

// 256-thread exclusive scan; sh must hold 8 unsigned
__device__ __forceinline__ unsigned block_scan_excl_256(unsigned v, unsigned* sh) {
    int lane = threadIdx.x & 31, w = threadIdx.x >> 5;
    unsigned x = v;
    #pragma unroll
    for (int o = 1; o < 32; o <<= 1) {
        unsigned y = __shfl_up_sync(0xFFFFFFFFu, x, o);
        if (lane >= o) x += y;
    }
    if (lane == 31) sh[w] = x;
    __syncthreads();
    if (w == 0 && lane < 8) {
        unsigned s = sh[lane], xx = s;
        #pragma unroll
        for (int o = 1; o < 8; o <<= 1) {
            unsigned y = __shfl_up_sync(0x000000FFu, xx, o);
            if (lane >= o) xx += y;
        }
        sh[lane] = xx - s;
    }
    __syncthreads();
    return (x - v) + sh[w];
}

// ================= K1: keys + top-16 histogram + fused select =================
__global__ void k1(const float* __restrict__ dp,
                   const float* __restrict__ rg,
                   const float* __restrict__ mp) {
    int t = threadIdx.x;
    int i = blockIdx.x * 256 + t;
    __shared__ unsigned scnt;
    if (t == 0) scnt = 0;
    __syncthreads();

    float r = rg[i], m = mp[i], d = dp[i];
    bool valid = (r > 0.0f) && (m > 1e-7f) && (r < 80.0f);
    unsigned key = 0xFFFFFFFFu;
    if (valid) {
        key = __float_as_uint(fabsf(d - r));
        atomicAdd(&g_histA[key >> 16], 1u);
    }
    g_key[i] = key;
    unsigned bal = __ballot_sync(0xFFFFFFFFu, valid);
    if ((t & 31) == 0 && bal) atomicAdd(&scnt, (unsigned)__popc(bal));
    __syncthreads();
    if (t == 0 && scnt) atomicAdd(&g_nvalid, scnt);

    // last-block ticket
    __threadfence();
    __syncthreads();
    __shared__ unsigned s_last;
    if (t == 0) s_last = (atomicAdd(&g_cnt1, 1u) == gridDim.x - 1u) ? 1u : 0u;
    __syncthreads();
    if (!s_last) return;

    unsigned n = g_nvalid;
    if (t == 0) { g_cnt1 = 0; g_nvalid = 0; }
    if (n == 0) {
        if (t == 0) { g_empty = 1u; g_prefTop[0] = g_prefTop[1] = 0xFFFFFFFFu; }
        return;
    }
    if (t == 0) g_empty = 0u;
    unsigned r0 = (n - 1) >> 1, r1 = n >> 1;

    // 256 threads x 256 bins
    const uint4* h4 = (const uint4*)g_histA;
    unsigned lsum = 0;
    for (int k = 0; k < 64; k++) {
        uint4 v = h4[t * 64 + k];
        lsum += v.x + v.y + v.z + v.w;
    }
    __shared__ unsigned sh[8];
    unsigned excl = block_scan_excl_256(lsum, sh);

    #pragma unroll
    for (int jr = 0; jr < 2; jr++) {
        unsigned rr = jr ? r1 : r0;
        if (rr >= excl && rr < excl + lsum) {
            unsigned run = excl;
            for (int k = 0; k < 256; k++) {
                unsigned c = g_histA[t * 256 + k];
                if (rr < run + c) { g_prefTop[jr] = t * 256 + k; g_rankLow[jr] = rr - run; break; }
                run += c;
            }
        }
    }
}

// ================= K2: low-16 histogram + fused final select =================
__global__ void k2() {
    int t = threadIdx.x;
    int i = blockIdx.x * 256 + t;
    unsigned top0 = g_prefTop[0], top1 = g_prefTop[1];

    unsigned key = g_key[i];
    unsigned top = key >> 16;
    if (top == top0)       atomicAdd(&g_histB[0][key & 0xFFFFu], 1u);
    else if (top == top1)  atomicAdd(&g_histB[1][key & 0xFFFFu], 1u);

    if (i < 65536) g_histA[i] = 0;     // restore histA zero-invariant for next replay

    __threadfence();
    __syncthreads();
    __shared__ unsigned s_last;
    if (t == 0) s_last = (atomicAdd(&g_cnt2, 1u) == gridDim.x - 1u) ? 1u : 0u;
    __syncthreads();
    if (!s_last) return;

    __shared__ unsigned sh[8];
    __shared__ unsigned s_med[2];
    unsigned empty = g_empty;
    if (!empty) {
        bool same = (top0 == top1);
        // scan histB[0], locate rank0 (and rank1 if same prefix)
        {
            unsigned lsum = 0;
            for (int k = 0; k < 64; k++) {
                uint4 v = ((const uint4*)g_histB[0])[t * 64 + k];
                lsum += v.x + v.y + v.z + v.w;
            }
            unsigned excl = block_scan_excl_256(lsum, sh);
            int njr = same ? 2 : 1;
            for (int jr = 0; jr < njr; jr++) {
                unsigned rr = g_rankLow[jr];
                if (rr >= excl && rr < excl + lsum) {
                    unsigned run = excl;
                    for (int k = 0; k < 256; k++) {
                        unsigned c = g_histB[0][t * 256 + k];
                        if (rr < run + c) { s_med[jr] = (top0 << 16) | (unsigned)(t * 256 + k); break; }
                        run += c;
                    }
                }
            }
        }
        if (!same) {
            __syncthreads();
            unsigned lsum = 0;
            for (int k = 0; k < 64; k++) {
                uint4 v = ((const uint4*)g_histB[1])[t * 64 + k];
                lsum += v.x + v.y + v.z + v.w;
            }
            unsigned excl = block_scan_excl_256(lsum, sh);
            unsigned rr = g_rankLow[1];
            if (rr >= excl && rr < excl + lsum) {
                unsigned run = excl;
                for (int k = 0; k < 256; k++) {
                    unsigned c = g_histB[1][t * 256 + k];
                    if (rr < run + c) { s_med[1] = (top1 << 16) | (unsigned)(t * 256 + k); break; }
                    run += c;
                }
            }
        }
    }
    __syncthreads();
    if (t == 0) {
        float thr = -1.0f;
        if (!empty) {
            float med = 0.5f * (__uint_as_float(s_med[0]) + __uint_as_float(s_med[1]));
            thr = 100.0f * med;
        }
        g_thresh = thr;
        g_sums[0] = g_sums[1] = g_sums[2] = g_sums[3] = 0.0f;
        g_cnt2 = 0;
    }
}

// ============ K3: fused depth loss + pack loss + finalize + histB zero ============
__global__ void k3(const float4* __restrict__ ds4,
                   const float4* __restrict__ vw4,
                   const int*    __restrict__ rih,
                   const float*  __restrict__ rg,
                   const float*  __restrict__ dp,
                   float*        __restrict__ out) {
    int t = threadIdx.x;
    int gtid = blockIdx.x * 256 + t;
    int lane = t & 31, wid = t >> 5;

    // restore histB zero-invariant (2*64K words spread over the grid)
    if (gtid < 131072) ((unsigned*)g_histB)[gtid] = 0;

    const float thr = g_thresh;

    // ---- depth loss part (first 131072 threads) ----
    float dm = 0.0f, mm = 0.0f;
    if (gtid < N_RAYS_C) {
        float kf = __uint_as_float(g_key[gtid]);    // NaN if invalid -> compare false
        if (kf < thr) {
            mm = 1.0f;
            dm = fabsf(log1pf(dp[gtid]) - log1pf(rg[gtid]));
        }
    }

    // ---- pack loss: one warp per pack ----
    float accn = 0.0f, acce = 0.0f;
    int gw = blockIdx.x * 8 + wid;
    int nwarps = gridDim.x * 8;
    for (int p = gw; p < N_HIT_C; p += nwarps) {
        int ray = rih[p];
        float gt = rg[ray];
        float mh = (__uint_as_float(g_key[ray]) < thr) ? 1.0f : 0.0f;
        if (mh == 0.0f) continue;
        float4 d4 = ds4[p * 32 + lane];
        if (d4.x - gt > 1.0f) continue;         // sorted chunk entirely past +sigma
        float4 w4 = vw4[p * 32 + lane];
        float ln = 0.0f, le = 0.0f;
        #pragma unroll
        for (int c = 0; c < 4; c++) {
            float d = (&d4.x)[c], w = (&w4.x)[c];
            float x = d - gt;
            if (fabsf(x) <= 1.0f) {
                float pdf = __expf(-4.5f * x * x) * 1.1968268412042982f; // 3/sqrt(2pi)
                float td = w - pdf;
                ln += td * td;
            } else if (x < -1.0f) {
                le += w * w;
            }
        }
        accn += ln;
        acce += le;
    }

    // ---- combined block reduction (4 accumulators) ----
    #pragma unroll
    for (int o = 16; o; o >>= 1) {
        dm   += __shfl_down_sync(0xFFFFFFFFu, dm,   o);
        mm   += __shfl_down_sync(0xFFFFFFFFu, mm,   o);
        accn += __shfl_down_sync(0xFFFFFFFFu, accn, o);
        acce += __shfl_down_sync(0xFFFFFFFFu, acce, o);
    }
    __shared__ float s0[8], s1[8], s2[8], s3[8];
    if (lane == 0) { s0[wid] = dm; s1[wid] = mm; s2[wid] = accn; s3[wid] = acce; }
    __syncthreads();
    if (t == 0) {
        float a = 0, b = 0, c = 0, e = 0;
        #pragma unroll
        for (int k = 0; k < 8; k++) { a += s0[k]; b += s1[k]; c += s2[k]; e += s3[k]; }
        atomicAdd(&g_sums[0], a);
        atomicAdd(&g_sums[1], b);
        atomicAdd(&g_sums[2], c);
        atomicAdd(&g_sums[3], e);
    }

    // ---- last block finalizes ----
    __threadfence();
    __syncthreads();
    __shared__ unsigned s_last;
    if (t == 0) s_last = (atomicAdd(&g_cnt3, 1u) == gridDim.x - 1u) ? 1u : 0u;
    __syncthreads();
    if (s_last && t == 0) {
        out[0] = g_sums[0] / fmaxf(g_sums[1], 1.0f);           // W_DEPTH = 1
        out[1] = 0.1f * (g_sums[2] * (1.0f / 65536.0f));       // W_LOS * mean
        out[2] = 0.1f * (g_sums[3] * (1.0f / 65536.0f));
        g_cnt3 = 0;
    }
}

extern "C" void kernel_launch(void* const* d_in, const int* in_sizes, int n_in,
                              void* d_out, int out_size) {
    const float* dp  = (const float*)d_in[0];   // depth_pred   [131072]
    const float* rg  = (const float*)d_in[1];   // ranges       [131072]
    const float* mp  = (const float*)d_in[2];   // mask_pred    [131072]
    const float* ds  = (const float*)d_in[3];   // depth_samples[8388608]
    const float* vw  = (const float*)d_in[4];   // vw           [8388608]
    const int*   rih = (const int*)d_in[5];     // rays_inds_hit[65536]
    float* out = (float*)d_out;

    k1<<<512, 256>>>(dp, rg, mp);
    k2<<<512, 256>>>();
    k3<<<1216, 256>>>((const float4*)ds, (const float4*)vw, rih, rg, dp, out);
}

// round 3
// speedup vs baseline: 1.7993x; 1.7993x over previous
#include <cuda_runtime.h>
#include <math.h>

#define N_RAYS_C 131072
#define N_HIT_C  65536

// ---------------- device state (zero at load; every replay restores zeros)
__device__ unsigned g_key[N_RAYS_C];          // err bits (valid) or 0xFFFFFFFF
__device__ __align__(16) unsigned g_h1[2048];       // stage-1 hist (top 11 bits)
__device__ __align__(16) unsigned g_h2[2][2048];    // stage-2 hists (mid 11 bits)
__device__ __align__(16) unsigned g_h3[2][1024];    // stage-3 hists (low 10 bits)
__device__ unsigned g_nvalid;
__device__ unsigned g_cnt1, g_cnt2, g_cnt3, g_cnt4;
__device__ unsigned g_prefix[2];              // accumulated high-bit prefix
__device__ unsigned g_rank[2];                // residual rank within prefix
__device__ unsigned g_empty;
__device__ float    g_thresh;
__device__ float    g_sums[4];                // sum_dm, sum_m, acc_neighbor, acc_empty

// 256-thread exclusive scan; sh must hold 8 unsigned
__device__ __forceinline__ unsigned block_scan_excl_256(unsigned v, unsigned* sh) {
    int lane = threadIdx.x & 31, w = threadIdx.x >> 5;
    unsigned x = v;
    #pragma unroll
    for (int o = 1; o < 32; o <<= 1) {
        unsigned y = __shfl_up_sync(0xFFFFFFFFu, x, o);
        if (lane >= o) x += y;
    }
    if (lane == 31) sh[w] = x;
    __syncthreads();
    if (w == 0 && lane < 8) {
        unsigned s = sh[lane], xx = s;
        #pragma unroll
        for (int o = 1; o < 8; o <<= 1) {
            unsigned y = __shfl_up_sync(0x000000FFu, xx, o);
            if (lane >= o) xx += y;
        }
        sh[lane] = xx - s;
    }
    __syncthreads();
    return (x - v) + sh[w];
}

// last-block ticket
__device__ __forceinline__ bool last_block(unsigned* cnt) {
    __threadfence();
    __syncthreads();
    __shared__ unsigned s_last;
    if (threadIdx.x == 0) s_last = (atomicAdd(cnt, 1u) == gridDim.x - 1u) ? 1u : 0u;
    __syncthreads();
    if (!s_last) return false;
    if (threadIdx.x == 0) *cnt = 0;
    return true;
}

// ================= K1: keys + stage-1 hist (2048 bins) + fused select =================
__global__ void k1(const float* __restrict__ dp,
                   const float* __restrict__ rg,
                   const float* __restrict__ mp) {
    __shared__ unsigned sh[2048];
    __shared__ unsigned scnt;
    int t = threadIdx.x;
    for (int b = t; b < 2048; b += 256) sh[b] = 0;
    if (t == 0) scnt = 0;
    __syncthreads();

    int i = blockIdx.x * 256 + t;
    float r = rg[i], m = mp[i], d = dp[i];
    bool valid = (r > 0.0f) && (m > 1e-7f) && (r < 80.0f);
    unsigned key = 0xFFFFFFFFu;
    if (valid) {
        key = __float_as_uint(fabsf(d - r));
        atomicAdd(&sh[key >> 21], 1u);
    }
    g_key[i] = key;
    unsigned bal = __ballot_sync(0xFFFFFFFFu, valid);
    if ((t & 31) == 0 && bal) atomicAdd(&scnt, (unsigned)__popc(bal));
    __syncthreads();
    for (int b = t; b < 2048; b += 256) {
        unsigned c = sh[b];
        if (c) atomicAdd(&g_h1[b], c);
    }
    if (t == 0 && scnt) atomicAdd(&g_nvalid, scnt);

    if (!last_block(&g_cnt1)) return;

    // ---- fused select over 2048 bins (8 per thread, in registers) ----
    unsigned n = g_nvalid;
    if (t == 0) g_nvalid = 0;
    unsigned c[8];
    unsigned lsum = 0;
    #pragma unroll
    for (int k = 0; k < 8; k++) { c[k] = g_h1[t * 8 + k]; lsum += c[k]; }
    // re-zero for next replay (values captured in regs)
    #pragma unroll
    for (int k = 0; k < 8; k++) g_h1[t * 8 + k] = 0;

    if (n == 0) {
        if (t == 0) { g_empty = 1u; g_prefix[0] = g_prefix[1] = 0xFFFFFFFFu; }
        return;
    }
    if (t == 0) g_empty = 0u;

    __shared__ unsigned shs[8];
    unsigned excl = block_scan_excl_256(lsum, shs);
    unsigned ranks[2] = { (n - 1) >> 1, n >> 1 };
    #pragma unroll
    for (int jr = 0; jr < 2; jr++) {
        unsigned rr = ranks[jr];
        if (rr >= excl && rr < excl + lsum) {
            unsigned run = excl;
            #pragma unroll
            for (int k = 0; k < 8; k++) {
                if (rr < run + c[k]) {
                    g_prefix[jr] = (unsigned)(t * 8 + k) << 21;
                    g_rank[jr]   = rr - run;
                    break;
                }
                run += c[k];
            }
        }
    }
}

// ================= K2: stage-2 refine (mid 11 bits) + fused select =================
__global__ void k2() {
    __shared__ unsigned sh[2][2048];
    int t = threadIdx.x;
    for (int b = t; b < 4096; b += 256) ((unsigned*)sh)[b] = 0;
    __syncthreads();

    unsigned p0 = g_prefix[0], p1 = g_prefix[1];
    int i = blockIdx.x * 256 + t;
    unsigned key = g_key[i];
    unsigned hi = key & 0xFFE00000u;
    if (hi == p0)      atomicAdd(&sh[0][(key >> 10) & 0x7FFu], 1u);
    else if (hi == p1) atomicAdd(&sh[1][(key >> 10) & 0x7FFu], 1u);
    __syncthreads();
    for (int b = t; b < 2048; b += 256) {
        if (sh[0][b]) atomicAdd(&g_h2[0][b], sh[0][b]);
        if (sh[1][b]) atomicAdd(&g_h2[1][b], sh[1][b]);
    }

    if (!last_block(&g_cnt2)) return;
    if (g_empty) return;

    bool same = (p0 == p1);
    __shared__ unsigned shs[8];
    for (int j = 0; j < 2; j++) {
        if (j == 1 && same) break;
        unsigned c[8];
        unsigned lsum = 0;
        #pragma unroll
        for (int k = 0; k < 8; k++) { c[k] = g_h2[j][t * 8 + k]; lsum += c[k]; }
        #pragma unroll
        for (int k = 0; k < 8; k++) g_h2[j][t * 8 + k] = 0;  // re-zero
        unsigned excl = block_scan_excl_256(lsum, shs);
        #pragma unroll
        for (int jr = 0; jr < 2; jr++) {
            int hsel = same ? 0 : jr;
            if (hsel != j) continue;
            unsigned rr = g_rank[jr];
            if (rr >= excl && rr < excl + lsum) {
                unsigned run = excl;
                #pragma unroll
                for (int k = 0; k < 8; k++) {
                    if (rr < run + c[k]) {
                        atomicExch(&g_prefix[jr], g_prefix[jr] | ((unsigned)(t * 8 + k) << 10));
                        atomicExch(&g_rank[jr], rr - run);
                        break;
                    }
                    run += c[k];
                }
            }
        }
        __syncthreads();
    }
    // if same: hist[1] never touched (stays zero) — nothing to re-zero
    if (same) {
        #pragma unroll
        for (int k = 0; k < 8; k++) g_h2[1][t * 8 + k] = 0;
    }
}

// ================= K3: stage-3 refine (low 10 bits) + fused select -> thresh =================
__global__ void k3() {
    __shared__ unsigned sh[2][1024];
    int t = threadIdx.x;
    for (int b = t; b < 2048; b += 256) ((unsigned*)sh)[b] = 0;
    __syncthreads();

    unsigned p0 = g_prefix[0], p1 = g_prefix[1];
    int i = blockIdx.x * 256 + t;
    unsigned key = g_key[i];
    unsigned hi = key & 0xFFFFFC00u;
    if (hi == p0)      atomicAdd(&sh[0][key & 0x3FFu], 1u);
    else if (hi == p1) atomicAdd(&sh[1][key & 0x3FFu], 1u);
    __syncthreads();
    for (int b = t; b < 1024; b += 256) {
        if (sh[0][b]) atomicAdd(&g_h3[0][b], sh[0][b]);
        if (sh[1][b]) atomicAdd(&g_h3[1][b], sh[1][b]);
    }

    if (!last_block(&g_cnt3)) return;

    __shared__ unsigned shs[8];
    __shared__ unsigned s_med[2];
    if (!g_empty) {
        bool same = (p0 == p1);
        for (int j = 0; j < 2; j++) {
            unsigned c[4];
            unsigned lsum = 0;
            #pragma unroll
            for (int k = 0; k < 4; k++) { c[k] = g_h3[j][t * 4 + k]; lsum += c[k]; }
            #pragma unroll
            for (int k = 0; k < 4; k++) g_h3[j][t * 4 + k] = 0;  // re-zero
            if (j == 1 && same) break;
            unsigned excl = block_scan_excl_256(lsum, shs);
            #pragma unroll
            for (int jr = 0; jr < 2; jr++) {
                int hsel = same ? 0 : jr;
                if (hsel != j) continue;
                unsigned rr = g_rank[jr];
                if (rr >= excl && rr < excl + lsum) {
                    unsigned run = excl;
                    #pragma unroll
                    for (int k = 0; k < 4; k++) {
                        if (rr < run + c[k]) {
                            s_med[jr] = g_prefix[jr] | (unsigned)(t * 4 + k);
                            break;
                        }
                        run += c[k];
                    }
                }
            }
            __syncthreads();
        }
    }
    __syncthreads();
    if (t == 0) {
        float thr = -1.0f;
        if (!g_empty) {
            float med = 0.5f * (__uint_as_float(s_med[0]) + __uint_as_float(s_med[1]));
            thr = 100.0f * med;
        }
        g_thresh = thr;
        g_sums[0] = g_sums[1] = g_sums[2] = g_sums[3] = 0.0f;
    }
}

// ============ K4: fused depth loss + pack loss + finalize ============
__global__ void k4(const float4* __restrict__ ds4,
                   const float4* __restrict__ vw4,
                   const int*    __restrict__ rih,
                   const float*  __restrict__ rg,
                   const float*  __restrict__ dp,
                   float*        __restrict__ out) {
    int t = threadIdx.x;
    int gtid = blockIdx.x * 256 + t;
    int lane = t & 31, wid = t >> 5;
    const float thr = g_thresh;

    // ---- depth loss part (first 131072 threads) ----
    float dm = 0.0f, mm = 0.0f;
    if (gtid < N_RAYS_C) {
        float kf = __uint_as_float(g_key[gtid]);    // NaN if invalid -> compare false
        if (kf < thr) {
            mm = 1.0f;
            dm = fabsf(log1pf(dp[gtid]) - log1pf(rg[gtid]));
        }
    }

    // ---- pack loss: one warp per pack ----
    float accn = 0.0f, acce = 0.0f;
    int gw = blockIdx.x * 8 + wid;
    int nwarps = gridDim.x * 8;
    for (int p = gw; p < N_HIT_C; p += nwarps) {
        int ray = rih[p];
        float gt = rg[ray];
        if (!(__uint_as_float(g_key[ray]) < thr)) continue;   // masked-out ray
        float4 d4 = ds4[p * 32 + lane];
        if (d4.x - gt > 1.0f) continue;         // sorted chunk entirely past +sigma
        float4 w4 = vw4[p * 32 + lane];
        float ln = 0.0f, le = 0.0f;
        #pragma unroll
        for (int c = 0; c < 4; c++) {
            float d = (&d4.x)[c], w = (&w4.x)[c];
            float x = d - gt;
            if (fabsf(x) <= 1.0f) {
                float pdf = __expf(-4.5f * x * x) * 1.1968268412042982f; // 3/sqrt(2pi)
                float td = w - pdf;
                ln += td * td;
            } else if (x < -1.0f) {
                le += w * w;
            }
        }
        accn += ln;
        acce += le;
    }

    // ---- combined block reduction (4 accumulators) ----
    #pragma unroll
    for (int o = 16; o; o >>= 1) {
        dm   += __shfl_down_sync(0xFFFFFFFFu, dm,   o);
        mm   += __shfl_down_sync(0xFFFFFFFFu, mm,   o);
        accn += __shfl_down_sync(0xFFFFFFFFu, accn, o);
        acce += __shfl_down_sync(0xFFFFFFFFu, acce, o);
    }
    __shared__ float s0[8], s1[8], s2[8], s3[8];
    if (lane == 0) { s0[wid] = dm; s1[wid] = mm; s2[wid] = accn; s3[wid] = acce; }
    __syncthreads();
    if (t == 0) {
        float a = 0, b = 0, c = 0, e = 0;
        #pragma unroll
        for (int k = 0; k < 8; k++) { a += s0[k]; b += s1[k]; c += s2[k]; e += s3[k]; }
        atomicAdd(&g_sums[0], a);
        atomicAdd(&g_sums[1], b);
        atomicAdd(&g_sums[2], c);
        atomicAdd(&g_sums[3], e);
    }

    if (!last_block(&g_cnt4)) return;
    if (t == 0) {
        out[0] = g_sums[0] / fmaxf(g_sums[1], 1.0f);           // W_DEPTH = 1
        out[1] = 0.1f * (g_sums[2] * (1.0f / 65536.0f));       // W_LOS * mean
        out[2] = 0.1f * (g_sums[3] * (1.0f / 65536.0f));
    }
}

extern "C" void kernel_launch(void* const* d_in, const int* in_sizes, int n_in,
                              void* d_out, int out_size) {
    const float* dp  = (const float*)d_in[0];   // depth_pred   [131072]
    const float* rg  = (const float*)d_in[1];   // ranges       [131072]
    const float* mp  = (const float*)d_in[2];   // mask_pred    [131072]
    const float* ds  = (const float*)d_in[3];   // depth_samples[8388608]
    const float* vw  = (const float*)d_in[4];   // vw           [8388608]
    const int*   rih = (const int*)d_in[5];     // rays_inds_hit[65536]
    float* out = (float*)d_out;

    k1<<<512, 256>>>(dp, rg, mp);
    k2<<<512, 256>>>();
    k3<<<512, 256>>>();
    k4<<<1216, 256>>>((const float4*)ds, (const float4*)vw, rih, rg, dp, out);
}

// round 4
// speedup vs baseline: 1.8896x; 1.0502x over previous
#include <cuda_runtime.h>
#include <math.h>

#define N_RAYS_C 131072
#define N_HIT_C  65536

// ---------------- device state (zero at load; every replay restores zeros)
__device__ unsigned g_key[N_RAYS_C];          // err bits (valid) or 0xFFFFFFFF
__device__ __align__(16) unsigned g_h1[2048];       // stage-1 hist (top 11 bits)
__device__ __align__(16) unsigned g_h2[2][2048];    // stage-2 hists (mid 11 bits)
__device__ __align__(16) unsigned g_h3[2][1024];    // stage-3 hists (low 10 bits)
__device__ unsigned g_nvalid;
__device__ unsigned g_cnt1, g_cnt2, g_cnt3, g_cnt4;
__device__ unsigned g_prefix[2];              // accumulated high-bit prefix
__device__ unsigned g_rank[2];                // residual rank within prefix
__device__ unsigned g_empty;
__device__ float    g_thresh;
__device__ float    g_sums[4];                // sum_dm, sum_m, acc_neighbor, acc_empty

// 256-thread exclusive scan; sh must hold 8 unsigned
__device__ __forceinline__ unsigned block_scan_excl_256(unsigned v, unsigned* sh) {
    int lane = threadIdx.x & 31, w = threadIdx.x >> 5;
    unsigned x = v;
    #pragma unroll
    for (int o = 1; o < 32; o <<= 1) {
        unsigned y = __shfl_up_sync(0xFFFFFFFFu, x, o);
        if (lane >= o) x += y;
    }
    if (lane == 31) sh[w] = x;
    __syncthreads();
    if (w == 0 && lane < 8) {
        unsigned s = sh[lane], xx = s;
        #pragma unroll
        for (int o = 1; o < 8; o <<= 1) {
            unsigned y = __shfl_up_sync(0x000000FFu, xx, o);
            if (lane >= o) xx += y;
        }
        sh[lane] = xx - s;
    }
    __syncthreads();
    return (x - v) + sh[w];
}

// last-block ticket
__device__ __forceinline__ bool last_block(unsigned* cnt) {
    __threadfence();
    __syncthreads();
    __shared__ unsigned s_last;
    if (threadIdx.x == 0) s_last = (atomicAdd(cnt, 1u) == gridDim.x - 1u) ? 1u : 0u;
    __syncthreads();
    if (!s_last) return false;
    if (threadIdx.x == 0) *cnt = 0;
    return true;
}

// ================= K1: keys + stage-1 hist (2048 bins) + fused select =================
__global__ void k1(const float* __restrict__ dp,
                   const float* __restrict__ rg,
                   const float* __restrict__ mp) {
    __shared__ unsigned sh[2048];
    __shared__ unsigned scnt;
    int t = threadIdx.x;
    for (int b = t; b < 2048; b += 256) sh[b] = 0;
    if (t == 0) scnt = 0;
    __syncthreads();

    int i = blockIdx.x * 256 + t;
    float r = rg[i], m = mp[i], d = dp[i];
    bool valid = (r > 0.0f) && (m > 1e-7f) && (r < 80.0f);
    unsigned key = 0xFFFFFFFFu;
    if (valid) {
        key = __float_as_uint(fabsf(d - r));
        atomicAdd(&sh[key >> 21], 1u);
    }
    g_key[i] = key;
    unsigned bal = __ballot_sync(0xFFFFFFFFu, valid);
    if ((t & 31) == 0 && bal) atomicAdd(&scnt, (unsigned)__popc(bal));
    __syncthreads();
    for (int b = t; b < 2048; b += 256) {
        unsigned c = sh[b];
        if (c) atomicAdd(&g_h1[b], c);
    }
    if (t == 0 && scnt) atomicAdd(&g_nvalid, scnt);

    if (!last_block(&g_cnt1)) return;

    // ---- fused select over 2048 bins (8 per thread, in registers) ----
    unsigned n = g_nvalid;
    if (t == 0) g_nvalid = 0;
    unsigned c[8];
    unsigned lsum = 0;
    #pragma unroll
    for (int k = 0; k < 8; k++) { c[k] = g_h1[t * 8 + k]; lsum += c[k]; }
    #pragma unroll
    for (int k = 0; k < 8; k++) g_h1[t * 8 + k] = 0;   // re-zero for next replay

    if (n == 0) {
        if (t == 0) { g_empty = 1u; g_prefix[0] = g_prefix[1] = 0xFFFFFFFFu; }
        return;
    }
    if (t == 0) g_empty = 0u;

    __shared__ unsigned shs[8];
    unsigned excl = block_scan_excl_256(lsum, shs);
    unsigned ranks[2] = { (n - 1) >> 1, n >> 1 };
    #pragma unroll
    for (int jr = 0; jr < 2; jr++) {
        unsigned rr = ranks[jr];
        if (rr >= excl && rr < excl + lsum) {
            unsigned run = excl;
            #pragma unroll
            for (int k = 0; k < 8; k++) {
                if (rr < run + c[k]) {
                    g_prefix[jr] = (unsigned)(t * 8 + k) << 21;
                    g_rank[jr]   = rr - run;
                    break;
                }
                run += c[k];
            }
        }
    }
}

// ================= K2: stage-2 refine (mid 11 bits) + fused select =================
__global__ void k2() {
    __shared__ unsigned sh[2][2048];
    int t = threadIdx.x;
    for (int b = t; b < 4096; b += 256) ((unsigned*)sh)[b] = 0;
    __syncthreads();

    unsigned p0 = g_prefix[0], p1 = g_prefix[1];
    int i = blockIdx.x * 256 + t;
    unsigned key = g_key[i];
    unsigned hi = key & 0xFFE00000u;
    if (hi == p0)      atomicAdd(&sh[0][(key >> 10) & 0x7FFu], 1u);
    else if (hi == p1) atomicAdd(&sh[1][(key >> 10) & 0x7FFu], 1u);
    __syncthreads();
    for (int b = t; b < 2048; b += 256) {
        if (sh[0][b]) atomicAdd(&g_h2[0][b], sh[0][b]);
        if (sh[1][b]) atomicAdd(&g_h2[1][b], sh[1][b]);
    }

    if (!last_block(&g_cnt2)) return;
    if (g_empty) return;

    bool same = (p0 == p1);
    __shared__ unsigned shs[8];
    for (int j = 0; j < 2; j++) {
        if (j == 1 && same) break;
        unsigned c[8];
        unsigned lsum = 0;
        #pragma unroll
        for (int k = 0; k < 8; k++) { c[k] = g_h2[j][t * 8 + k]; lsum += c[k]; }
        #pragma unroll
        for (int k = 0; k < 8; k++) g_h2[j][t * 8 + k] = 0;  // re-zero
        unsigned excl = block_scan_excl_256(lsum, shs);
        #pragma unroll
        for (int jr = 0; jr < 2; jr++) {
            int hsel = same ? 0 : jr;
            if (hsel != j) continue;
            unsigned rr = g_rank[jr];
            if (rr >= excl && rr < excl + lsum) {
                unsigned run = excl;
                #pragma unroll
                for (int k = 0; k < 8; k++) {
                    if (rr < run + c[k]) {
                        atomicExch(&g_prefix[jr], g_prefix[jr] | ((unsigned)(t * 8 + k) << 10));
                        atomicExch(&g_rank[jr], rr - run);
                        break;
                    }
                    run += c[k];
                }
            }
        }
        __syncthreads();
    }
    if (same) {
        #pragma unroll
        for (int k = 0; k < 8; k++) g_h2[1][t * 8 + k] = 0;
    }
}

// ================= K3: stage-3 refine (low 10 bits) + fused select -> thresh =================
__global__ void k3() {
    __shared__ unsigned sh[2][1024];
    int t = threadIdx.x;
    for (int b = t; b < 2048; b += 256) ((unsigned*)sh)[b] = 0;
    __syncthreads();

    unsigned p0 = g_prefix[0], p1 = g_prefix[1];
    int i = blockIdx.x * 256 + t;
    unsigned key = g_key[i];
    unsigned hi = key & 0xFFFFFC00u;
    if (hi == p0)      atomicAdd(&sh[0][key & 0x3FFu], 1u);
    else if (hi == p1) atomicAdd(&sh[1][key & 0x3FFu], 1u);
    __syncthreads();
    for (int b = t; b < 1024; b += 256) {
        if (sh[0][b]) atomicAdd(&g_h3[0][b], sh[0][b]);
        if (sh[1][b]) atomicAdd(&g_h3[1][b], sh[1][b]);
    }

    if (!last_block(&g_cnt3)) return;

    __shared__ unsigned shs[8];
    __shared__ unsigned s_med[2];
    if (!g_empty) {
        bool same = (p0 == p1);
        for (int j = 0; j < 2; j++) {
            unsigned c[4];
            unsigned lsum = 0;
            #pragma unroll
            for (int k = 0; k < 4; k++) { c[k] = g_h3[j][t * 4 + k]; lsum += c[k]; }
            #pragma unroll
            for (int k = 0; k < 4; k++) g_h3[j][t * 4 + k] = 0;  // re-zero
            if (j == 1 && same) break;
            unsigned excl = block_scan_excl_256(lsum, shs);
            #pragma unroll
            for (int jr = 0; jr < 2; jr++) {
                int hsel = same ? 0 : jr;
                if (hsel != j) continue;
                unsigned rr = g_rank[jr];
                if (rr >= excl && rr < excl + lsum) {
                    unsigned run = excl;
                    #pragma unroll
                    for (int k = 0; k < 4; k++) {
                        if (rr < run + c[k]) {
                            s_med[jr] = g_prefix[jr] | (unsigned)(t * 4 + k);
                            break;
                        }
                        run += c[k];
                    }
                }
            }
            __syncthreads();
        }
    }
    __syncthreads();
    if (t == 0) {
        float thr = -1.0f;
        if (!g_empty) {
            float med = 0.5f * (__uint_as_float(s_med[0]) + __uint_as_float(s_med[1]));
            thr = 100.0f * med;
        }
        g_thresh = thr;
        g_sums[0] = g_sums[1] = g_sums[2] = g_sums[3] = 0.0f;
    }
}

// one pack's 4-float chunk contribution (branchless, predicated)
__device__ __forceinline__ void pack_chunk(float4 d4, float4 w4, float gt, bool msk,
                                           float& accn, float& acce) {
    float ln = 0.0f, le = 0.0f;
    #pragma unroll
    for (int c = 0; c < 4; c++) {
        float d = (&d4.x)[c], w = (&w4.x)[c];
        float x = d - gt;
        float pdf = __expf(-4.5f * x * x) * 1.1968268412042982f;   // 3/sqrt(2pi)
        float td = w - pdf;
        ln += (fabsf(x) <= 1.0f) ? td * td : 0.0f;
        le += (x < -1.0f) ? w * w : 0.0f;
    }
    if (msk) { accn += ln; acce += le; }
}

// ============ K4: fused depth loss + pack loss (unroll-2, batched loads) + finalize ============
__global__ void k4(const float4* __restrict__ ds4,
                   const float4* __restrict__ vw4,
                   const int*    __restrict__ rih,
                   const float*  __restrict__ rg,
                   const float*  __restrict__ dp,
                   float*        __restrict__ out) {
    int t = threadIdx.x;
    int gtid = blockIdx.x * 256 + t;
    int lane = t & 31, wid = t >> 5;
    const float thr = g_thresh;

    // ---- depth loss part (first 131072 threads) ----
    float dm = 0.0f, mm = 0.0f;
    if (gtid < N_RAYS_C) {
        float kf = __uint_as_float(g_key[gtid]);    // NaN if invalid -> compare false
        if (kf < thr) {
            mm = 1.0f;
            dm = fabsf(log1pf(dp[gtid]) - log1pf(rg[gtid]));
        }
    }

    // ---- pack loss: one warp per pack, 2 packs per iteration for MLP ----
    float accn = 0.0f, acce = 0.0f;
    int nwarps = gridDim.x * 8;                 // 16384 with grid=2048
    int gw = blockIdx.x * 8 + wid;
    for (int p = gw; p < N_HIT_C; p += 2 * nwarps) {
        int pb = p + nwarps;
        bool hb = (pb < N_HIT_C);
        // level 1: pack->ray indices (2 independent)
        int ray_a = rih[p];
        int ray_b = hb ? rih[pb] : ray_a;
        // level 2: 4 independent gathers
        float gt_a = rg[ray_a];
        float gt_b = rg[ray_b];
        float ka = __uint_as_float(g_key[ray_a]);
        float kb = __uint_as_float(g_key[ray_b]);
        // level 3: 4 independent 16B streaming loads
        float4 d4a = ds4[p * 32 + lane];
        float4 w4a = vw4[p * 32 + lane];
        float4 d4b, w4b;
        if (hb) { d4b = ds4[pb * 32 + lane]; w4b = vw4[pb * 32 + lane]; }
        // compute
        pack_chunk(d4a, w4a, gt_a, (ka < thr), accn, acce);
        if (hb) pack_chunk(d4b, w4b, gt_b, (kb < thr), accn, acce);
    }

    // ---- combined block reduction (4 accumulators) ----
    #pragma unroll
    for (int o = 16; o; o >>= 1) {
        dm   += __shfl_down_sync(0xFFFFFFFFu, dm,   o);
        mm   += __shfl_down_sync(0xFFFFFFFFu, mm,   o);
        accn += __shfl_down_sync(0xFFFFFFFFu, accn, o);
        acce += __shfl_down_sync(0xFFFFFFFFu, acce, o);
    }
    __shared__ float s0[8], s1[8], s2[8], s3[8];
    if (lane == 0) { s0[wid] = dm; s1[wid] = mm; s2[wid] = accn; s3[wid] = acce; }
    __syncthreads();
    if (t == 0) {
        float a = 0, b = 0, c = 0, e = 0;
        #pragma unroll
        for (int k = 0; k < 8; k++) { a += s0[k]; b += s1[k]; c += s2[k]; e += s3[k]; }
        atomicAdd(&g_sums[0], a);
        atomicAdd(&g_sums[1], b);
        atomicAdd(&g_sums[2], c);
        atomicAdd(&g_sums[3], e);
    }

    if (!last_block(&g_cnt4)) return;
    if (t == 0) {
        out[0] = g_sums[0] / fmaxf(g_sums[1], 1.0f);           // W_DEPTH = 1
        out[1] = 0.1f * (g_sums[2] * (1.0f / 65536.0f));       // W_LOS * mean
        out[2] = 0.1f * (g_sums[3] * (1.0f / 65536.0f));
    }
}

extern "C" void kernel_launch(void* const* d_in, const int* in_sizes, int n_in,
                              void* d_out, int out_size) {
    const float* dp  = (const float*)d_in[0];   // depth_pred   [131072]
    const float* rg  = (const float*)d_in[1];   // ranges       [131072]
    const float* mp  = (const float*)d_in[2];   // mask_pred    [131072]
    const float* ds  = (const float*)d_in[3];   // depth_samples[8388608]
    const float* vw  = (const float*)d_in[4];   // vw           [8388608]
    const int*   rih = (const int*)d_in[5];     // rays_inds_hit[65536]
    float* out = (float*)d_out;

    k1<<<512, 256>>>(dp, rg, mp);
    k2<<<512, 256>>>();
    k3<<<512, 256>>>();
    k4<<<2048, 256>>>((const float4*)ds, (const float4*)vw, rih, rg, dp, out);
}

// round 7
// speedup vs baseline: 2.0808x; 1.1012x over previous
#include <cuda_runtime.h>
#include <math.h>

#define N_RAYS_C 131072
#define N_HIT_C  65536

// ---------------- device state (zero at load; every replay restores zeros)
__device__ unsigned g_key[N_RAYS_C];          // err bits (valid) or 0xFFFFFFFF
__device__ float2   g_pack[N_HIT_C];          // per-pack {gt, key_bits_as_float}
__device__ __align__(16) unsigned g_h1[2048];       // stage-1 hist (top 11 bits)
__device__ __align__(16) unsigned g_h2[2][2048];    // stage-2 hists (mid 11 bits)
__device__ __align__(16) unsigned g_h3[2][1024];    // stage-3 hists (low 10 bits)
__device__ unsigned g_nvalid;
__device__ unsigned g_cnt1, g_cnt2, g_cnt3, g_cnt4;
__device__ unsigned g_prefix[2];              // accumulated high-bit prefix
__device__ unsigned g_rank[2];                // residual rank within prefix
__device__ unsigned g_empty;
__device__ float    g_thresh;
__device__ float    g_sums[4];                // sum_dm, sum_m, acc_neighbor, acc_empty

// 256-thread exclusive scan; sh must hold 8 unsigned
__device__ __forceinline__ unsigned block_scan_excl_256(unsigned v, unsigned* sh) {
    int lane = threadIdx.x & 31, w = threadIdx.x >> 5;
    unsigned x = v;
    #pragma unroll
    for (int o = 1; o < 32; o <<= 1) {
        unsigned y = __shfl_up_sync(0xFFFFFFFFu, x, o);
        if (lane >= o) x += y;
    }
    if (lane == 31) sh[w] = x;
    __syncthreads();
    if (w == 0 && lane < 8) {
        unsigned s = sh[lane], xx = s;
        #pragma unroll
        for (int o = 1; o < 8; o <<= 1) {
            unsigned y = __shfl_up_sync(0x000000FFu, xx, o);
            if (lane >= o) xx += y;
        }
        sh[lane] = xx - s;
    }
    __syncthreads();
    return (x - v) + sh[w];
}

// last-block ticket
__device__ __forceinline__ bool last_block(unsigned* cnt) {
    __threadfence();
    __syncthreads();
    __shared__ unsigned s_last;
    if (threadIdx.x == 0) s_last = (atomicAdd(cnt, 1u) == gridDim.x - 1u) ? 1u : 0u;
    __syncthreads();
    if (!s_last) return false;
    if (threadIdx.x == 0) *cnt = 0;
    return true;
}

// ================= K1: keys + stage-1 hist (2048 bins) + fused select =================
__global__ void k1(const float* __restrict__ dp,
                   const float* __restrict__ rg,
                   const float* __restrict__ mp) {
    __shared__ unsigned sh[2048];
    __shared__ unsigned scnt;
    int t = threadIdx.x;
    for (int b = t; b < 2048; b += 256) sh[b] = 0;
    if (t == 0) scnt = 0;
    __syncthreads();

    int i = blockIdx.x * 256 + t;
    float r = rg[i], m = mp[i], d = dp[i];
    bool valid = (r > 0.0f) && (m > 1e-7f) && (r < 80.0f);
    unsigned key = 0xFFFFFFFFu;
    if (valid) {
        key = __float_as_uint(fabsf(d - r));
        atomicAdd(&sh[key >> 21], 1u);
    }
    g_key[i] = key;
    unsigned bal = __ballot_sync(0xFFFFFFFFu, valid);
    if ((t & 31) == 0 && bal) atomicAdd(&scnt, (unsigned)__popc(bal));
    __syncthreads();
    for (int b = t; b < 2048; b += 256) {
        unsigned c = sh[b];
        if (c) atomicAdd(&g_h1[b], c);
    }
    if (t == 0 && scnt) atomicAdd(&g_nvalid, scnt);

    if (!last_block(&g_cnt1)) return;

    // ---- fused select over 2048 bins (8 per thread, in registers) ----
    unsigned n = g_nvalid;
    if (t == 0) g_nvalid = 0;
    unsigned c[8];
    unsigned lsum = 0;
    #pragma unroll
    for (int k = 0; k < 8; k++) { c[k] = g_h1[t * 8 + k]; lsum += c[k]; }
    #pragma unroll
    for (int k = 0; k < 8; k++) g_h1[t * 8 + k] = 0;   // re-zero for next replay

    if (n == 0) {
        if (t == 0) { g_empty = 1u; g_prefix[0] = g_prefix[1] = 0xFFFFFFFFu; }
        return;
    }
    if (t == 0) g_empty = 0u;

    __shared__ unsigned shs[8];
    unsigned excl = block_scan_excl_256(lsum, shs);
    unsigned ranks[2] = { (n - 1) >> 1, n >> 1 };
    #pragma unroll
    for (int jr = 0; jr < 2; jr++) {
        unsigned rr = ranks[jr];
        if (rr >= excl && rr < excl + lsum) {
            unsigned run = excl;
            #pragma unroll
            for (int k = 0; k < 8; k++) {
                if (rr < run + c[k]) {
                    g_prefix[jr] = (unsigned)(t * 8 + k) << 21;
                    g_rank[jr]   = rr - run;
                    break;
                }
                run += c[k];
            }
        }
    }
}

// ================= K2: stage-2 refine (mid 11 bits) + fused select =================
__global__ void k2() {
    __shared__ unsigned sh[2][2048];
    int t = threadIdx.x;
    for (int b = t; b < 4096; b += 256) ((unsigned*)sh)[b] = 0;
    __syncthreads();

    unsigned p0 = g_prefix[0], p1 = g_prefix[1];
    int i = blockIdx.x * 256 + t;
    unsigned key = g_key[i];
    unsigned hi = key & 0xFFE00000u;
    if (hi == p0)      atomicAdd(&sh[0][(key >> 10) & 0x7FFu], 1u);
    else if (hi == p1) atomicAdd(&sh[1][(key >> 10) & 0x7FFu], 1u);
    __syncthreads();
    for (int b = t; b < 2048; b += 256) {
        if (sh[0][b]) atomicAdd(&g_h2[0][b], sh[0][b]);
        if (sh[1][b]) atomicAdd(&g_h2[1][b], sh[1][b]);
    }

    if (!last_block(&g_cnt2)) return;
    if (g_empty) return;

    bool same = (p0 == p1);
    __shared__ unsigned shs[8];
    for (int j = 0; j < 2; j++) {
        if (j == 1 && same) break;
        unsigned c[8];
        unsigned lsum = 0;
        #pragma unroll
        for (int k = 0; k < 8; k++) { c[k] = g_h2[j][t * 8 + k]; lsum += c[k]; }
        #pragma unroll
        for (int k = 0; k < 8; k++) g_h2[j][t * 8 + k] = 0;  // re-zero
        unsigned excl = block_scan_excl_256(lsum, shs);
        #pragma unroll
        for (int jr = 0; jr < 2; jr++) {
            int hsel = same ? 0 : jr;
            if (hsel != j) continue;
            unsigned rr = g_rank[jr];
            if (rr >= excl && rr < excl + lsum) {
                unsigned run = excl;
                #pragma unroll
                for (int k = 0; k < 8; k++) {
                    if (rr < run + c[k]) {
                        atomicExch(&g_prefix[jr], g_prefix[jr] | ((unsigned)(t * 8 + k) << 10));
                        atomicExch(&g_rank[jr], rr - run);
                        break;
                    }
                    run += c[k];
                }
            }
        }
        __syncthreads();
    }
    if (same) {
        #pragma unroll
        for (int k = 0; k < 8; k++) g_h2[1][t * 8 + k] = 0;
    }
}

// ===== K3: stage-3 refine + fused select -> thresh; also precompute g_pack =====
__global__ void k3(const int* __restrict__ rih, const float* __restrict__ rg) {
    __shared__ unsigned sh[2][1024];
    int t = threadIdx.x;
    for (int b = t; b < 2048; b += 256) ((unsigned*)sh)[b] = 0;
    __syncthreads();

    unsigned p0 = g_prefix[0], p1 = g_prefix[1];
    int i = blockIdx.x * 256 + t;
    unsigned key = g_key[i];
    unsigned hi = key & 0xFFFFFC00u;
    if (hi == p0)      atomicAdd(&sh[0][key & 0x3FFu], 1u);
    else if (hi == p1) atomicAdd(&sh[1][key & 0x3FFu], 1u);

    // per-pack precompute: gathers overlap with histogram work
    if (i < N_HIT_C) {
        int ray = rih[i];
        g_pack[i] = make_float2(rg[ray], __uint_as_float(g_key[ray]));
    }

    __syncthreads();
    for (int b = t; b < 1024; b += 256) {
        if (sh[0][b]) atomicAdd(&g_h3[0][b], sh[0][b]);
        if (sh[1][b]) atomicAdd(&g_h3[1][b], sh[1][b]);
    }

    if (!last_block(&g_cnt3)) return;

    __shared__ unsigned shs[8];
    __shared__ unsigned s_med[2];
    if (!g_empty) {
        bool same = (p0 == p1);
        for (int j = 0; j < 2; j++) {
            unsigned c[4];
            unsigned lsum = 0;
            #pragma unroll
            for (int k = 0; k < 4; k++) { c[k] = g_h3[j][t * 4 + k]; lsum += c[k]; }
            #pragma unroll
            for (int k = 0; k < 4; k++) g_h3[j][t * 4 + k] = 0;  // re-zero
            if (j == 1 && same) break;
            unsigned excl = block_scan_excl_256(lsum, shs);
            #pragma unroll
            for (int jr = 0; jr < 2; jr++) {
                int hsel = same ? 0 : jr;
                if (hsel != j) continue;
                unsigned rr = g_rank[jr];
                if (rr >= excl && rr < excl + lsum) {
                    unsigned run = excl;
                    #pragma unroll
                    for (int k = 0; k < 4; k++) {
                        if (rr < run + c[k]) {
                            s_med[jr] = g_prefix[jr] | (unsigned)(t * 4 + k);
                            break;
                        }
                        run += c[k];
                    }
                }
            }
            __syncthreads();
        }
    }
    __syncthreads();
    if (t == 0) {
        float thr = -1.0f;
        if (!g_empty) {
            float med = 0.5f * (__uint_as_float(s_med[0]) + __uint_as_float(s_med[1]));
            thr = 100.0f * med;
        }
        g_thresh = thr;
        g_sums[0] = g_sums[1] = g_sums[2] = g_sums[3] = 0.0f;
    }
}

// one pack's 4-float chunk (branchless)
__device__ __forceinline__ void pack_chunk(float4 d4, float4 w4, float gt, bool msk,
                                           float& accn, float& acce) {
    float ln = 0.0f, le = 0.0f;
    #pragma unroll
    for (int c = 0; c < 4; c++) {
        float dd = (&d4.x)[c], w = (&w4.x)[c];
        float x = dd - gt;
        float pdf = __expf(-4.5f * x * x) * 1.1968268412042982f;   // 3/sqrt(2pi)
        float td = w - pdf;
        ln += (fabsf(x) <= 1.0f) ? td * td : 0.0f;
        le += (x < -1.0f) ? w * w : 0.0f;
    }
    if (msk) { accn += ln; acce += le; }
}

// ============ K4: fused depth loss + pack loss (4 packs/warp, all loads batched) ============
__global__ void __launch_bounds__(256)
k4(const float4* __restrict__ ds4, const float4* __restrict__ vw4,
   const float*  __restrict__ rg,  const float*  __restrict__ dp,
   float* __restrict__ out) {
    int t = threadIdx.x;
    int gtid = blockIdx.x * 256 + t;
    int lane = t & 31, wid = t >> 5;
    const float thr = g_thresh;

    // ---- depth loss (first 131072 threads) ----
    float dm = 0.0f, mm = 0.0f;
    if (gtid < N_RAYS_C) {
        float kf = __uint_as_float(g_key[gtid]);   // NaN if invalid -> compare false
        if (kf < thr) {
            mm = 1.0f;
            dm = fabsf(log1pf(dp[gtid]) - log1pf(rg[gtid]));
        }
    }

    // ---- pack loss: exactly 4 packs per warp, all loads batched up front ----
    const int NW = 2048 * 8;                  // total warps = 16384
    int gw = blockIdx.x * 8 + wid;            // 0..16383
    float2 gk[4];
    float4 dv[4], wv[4];
    #pragma unroll
    for (int k = 0; k < 4; k++) gk[k] = g_pack[gw + k * NW];       // warp-uniform 8B
    #pragma unroll
    for (int k = 0; k < 4; k++) dv[k] = ds4[(gw + k * NW) * 32 + lane];
    #pragma unroll
    for (int k = 0; k < 4; k++) wv[k] = vw4[(gw + k * NW) * 32 + lane];

    float accn = 0.0f, acce = 0.0f;
    #pragma unroll
    for (int k = 0; k < 4; k++)
        pack_chunk(dv[k], wv[k], gk[k].x, (gk[k].y < thr), accn, acce);

    // ---- combined block reduction (4 accumulators) ----
    #pragma unroll
    for (int o = 16; o; o >>= 1) {
        dm   += __shfl_down_sync(0xFFFFFFFFu, dm,   o);
        mm   += __shfl_down_sync(0xFFFFFFFFu, mm,   o);
        accn += __shfl_down_sync(0xFFFFFFFFu, accn, o);
        acce += __shfl_down_sync(0xFFFFFFFFu, acce, o);
    }
    __shared__ float s0[8], s1[8], s2[8], s3[8];
    if (lane == 0) { s0[wid] = dm; s1[wid] = mm; s2[wid] = accn; s3[wid] = acce; }
    __syncthreads();
    if (t == 0) {
        float a = 0, b = 0, c = 0, e = 0;
        #pragma unroll
        for (int k = 0; k < 8; k++) { a += s0[k]; b += s1[k]; c += s2[k]; e += s3[k]; }
        atomicAdd(&g_sums[0], a);
        atomicAdd(&g_sums[1], b);
        atomicAdd(&g_sums[2], c);
        atomicAdd(&g_sums[3], e);
    }

    if (!last_block(&g_cnt4)) return;
    if (t == 0) {
        out[0] = g_sums[0] / fmaxf(g_sums[1], 1.0f);           // W_DEPTH = 1
        out[1] = 0.1f * (g_sums[2] * (1.0f / 65536.0f));       // W_LOS * mean
        out[2] = 0.1f * (g_sums[3] * (1.0f / 65536.0f));
    }
}

extern "C" void kernel_launch(void* const* d_in, const int* in_sizes, int n_in,
                              void* d_out, int out_size) {
    const float* dp  = (const float*)d_in[0];   // depth_pred   [131072]
    const float* rg  = (const float*)d_in[1];   // ranges       [131072]
    const float* mp  = (const float*)d_in[2];   // mask_pred    [131072]
    const float* ds  = (const float*)d_in[3];   // depth_samples[8388608]
    const float* vw  = (const float*)d_in[4];   // vw           [8388608]
    const int*   rih = (const int*)d_in[5];     // rays_inds_hit[65536]
    float* out = (float*)d_out;

    k1<<<512, 256>>>(dp, rg, mp);
    k2<<<512, 256>>>();
    k3<<<512, 256>>>(rih, rg);
    k4<<<2048, 256>>>((const float4*)ds, (const float4*)vw, rg, dp, out);
}